// round 9
// baseline (speedup 1.0000x reference)
#include <cuda_runtime.h>
#include <cuda_bf16.h>
#include <math.h>

#define NND 512
#define SD  32
#define HM  64
#define TI  32    // i-rows per block
#define TJS 4     // j-cols per subtile
#define NSUB 8    // subtiles per block (block covers 32 j total)

// Scratch (device globals: no allocation allowed)
__device__ float g_A[NND * HM];     // row term  (incl. b_i*wbi)
__device__ float g_B[NND * HM];     // col term  (incl. b_j*wbj + mp_b1)
__device__ float g_msg[NND * SD];   // msg_sum
__device__ float g_h[NND * SD];     // node state (updated in place; blocks own disjoint nodes)

__device__ __forceinline__ float frelu(float x) { return fmaxf(x, 0.f); }

__device__ __forceinline__ unsigned packbf(float lo, float hi) {
    __nv_bfloat162 h = __floats2bfloat162_rn(lo, hi);
    return *reinterpret_cast<unsigned*>(&h);
}

__device__ __forceinline__ void mma16816(float c[4],
                                         unsigned a0, unsigned a1, unsigned a2, unsigned a3,
                                         unsigned b0, unsigned b1) {
    asm volatile(
        "mma.sync.aligned.m16n8k16.row.col.f32.bf16.bf16.f32 "
        "{%0,%1,%2,%3}, {%4,%5,%6,%7}, {%8,%9}, {%0,%1,%2,%3};"
        : "+f"(c[0]), "+f"(c[1]), "+f"(c[2]), "+f"(c[3])
        : "r"(a0), "r"(a1), "r"(a2), "r"(a3), "r"(b0), "r"(b1));
}

// ---------------------------------------------------------------- init h = 0
__global__ void init_kernel() {
    int idx = blockIdx.x * 256 + threadIdx.x;
    if (idx < NND * SD) g_h[idx] = 0.f;
}

// ------------------------------------------------- step-0 rank-term prep (h = g_h)
// A[i][k] = sum_d h[i][d]*W1[k][d]      + b[i]*W1[k][65]
// B[i][k] = sum_d h[i][d]*W1[k][32+d]   + b[i]*W1[k][66] + mp_b1[k]
__global__ void __launch_bounds__(64) prep_kernel(
    const float* __restrict__ hin, const float* __restrict__ b,
    const float* __restrict__ mp_W1, const float* __restrict__ mp_b1)
{
    __shared__ float sh[SD];
    const int i = blockIdx.x, t = threadIdx.x;
    if (t < SD) { sh[t] = hin[i * SD + t]; g_msg[i * SD + t] = 0.f; }
    __syncthreads();
    const float* row = mp_W1 + t * 67;
    float a = 0.f, bb = mp_b1[t];
#pragma unroll
    for (int d = 0; d < SD; d++) { a += row[d] * sh[d]; bb += row[32 + d] * sh[d]; }
    const float bi = b[i];
    g_A[i * HM + t] = a + bi * row[65];
    g_B[i * HM + t] = bb + bi * row[66];
}

// ---------------------------------------------------- pairwise message MLP (tensor cores)
// Block: 256 threads, covers 32 i-rows x 32 j-cols as 8 sequential subtiles of
// 32x4 (=128 pairs). Per subtile the warp layout is IDENTICAL to the proven R2
// kernel: warp w -> j_local = w>>1, rows (w&1)*16 .. +16. W2/W3/A/biases staged
// once per block; only B (256 f) and J (direct LDG) are per-subtile.
__global__ void __launch_bounds__(256) pair_mma_kernel(
    const float* __restrict__ J, const float* __restrict__ mp_W1,
    const float* __restrict__ W2, const float* __restrict__ b2,
    const float* __restrict__ W3, const float* __restrict__ b3)
{
    __shared__ __nv_bfloat16 sW2[HM * 72];   // [k2][k1], padded rows
    __shared__ __nv_bfloat16 sW3[SD * 72];   // [c][k2], padded rows
    __shared__ float sA[TI * 72];            // i-local x 64, padded
    __shared__ float sB[TJS * HM];           // j-local x 64 (per subtile)
    __shared__ float swJ[HM], sb2[HM], sb3[SD];

    const int t = threadIdx.x, w = t >> 5, l = t & 31;
    const int jbase = blockIdx.x * (TJS * NSUB), i0 = blockIdx.y * TI;

    for (int idx = t; idx < HM * HM; idx += 256)
        sW2[(idx >> 6) * 72 + (idx & 63)] = __float2bfloat16(W2[idx]);
    for (int idx = t; idx < SD * HM; idx += 256)
        sW3[(idx >> 6) * 72 + (idx & 63)] = __float2bfloat16(W3[idx]);
    for (int idx = t; idx < TI * HM; idx += 256)
        sA[(idx >> 6) * 72 + (idx & 63)] = g_A[(i0 + (idx >> 6)) * HM + (idx & 63)];
    if (t < HM) { swJ[t] = mp_W1[t * 67 + 64]; sb2[t] = b2[t]; }
    if (t < SD) sb3[t] = b3[t];

    const int jl = w >> 1;            // warp's j (local within subtile)
    const int g = l >> 2, q = l & 3;  // groupID, threadID-in-group
    const int ilo = (w & 1) * 16 + g; // i-local of fragment rows r and r+8
    const int ihi = ilo + 8;

    for (int sub = 0; sub < NSUB; sub++) {
        const int j0 = jbase + sub * TJS;
        __syncthreads();   // previous subtile done reading sB
        for (int idx = t; idx < TJS * HM; idx += 256)
            sB[idx] = g_B[(j0 + (idx >> 6)) * HM + (idx & 63)];
        __syncthreads();

        const float Jlo = J[(i0 + ilo) * NND + (j0 + jl)];
        const float Jhi = J[(i0 + ihi) * NND + (j0 + jl)];

        float C1[8][4];
#pragma unroll
        for (int nt = 0; nt < 8; nt++)
#pragma unroll
            for (int r = 0; r < 4; r++) C1[nt][r] = 0.f;

        // ---------------- stage 1: m2 accum = m1 @ W2^T
#pragma unroll
        for (int kt = 0; kt < 4; kt++) {
            const int c0 = kt * 16 + 2 * q;
            const float2 wj0 = *reinterpret_cast<const float2*>(&swJ[c0]);
            const float2 wj1 = *reinterpret_cast<const float2*>(&swJ[c0 + 8]);
            const float2 al0 = *reinterpret_cast<const float2*>(&sA[ilo * 72 + c0]);
            const float2 al1 = *reinterpret_cast<const float2*>(&sA[ilo * 72 + c0 + 8]);
            const float2 ah0 = *reinterpret_cast<const float2*>(&sA[ihi * 72 + c0]);
            const float2 ah1 = *reinterpret_cast<const float2*>(&sA[ihi * 72 + c0 + 8]);
            const float2 bb0 = *reinterpret_cast<const float2*>(&sB[jl * HM + c0]);
            const float2 bb1 = *reinterpret_cast<const float2*>(&sB[jl * HM + c0 + 8]);

            // m1 = relu(A_i + B_j + J*wJ), packed straight into A fragments
            unsigned a0 = packbf(frelu(fmaf(Jlo, wj0.x, al0.x + bb0.x)),
                                 frelu(fmaf(Jlo, wj0.y, al0.y + bb0.y)));
            unsigned a1 = packbf(frelu(fmaf(Jhi, wj0.x, ah0.x + bb0.x)),
                                 frelu(fmaf(Jhi, wj0.y, ah0.y + bb0.y)));
            unsigned a2 = packbf(frelu(fmaf(Jlo, wj1.x, al1.x + bb1.x)),
                                 frelu(fmaf(Jlo, wj1.y, al1.y + bb1.y)));
            unsigned a3 = packbf(frelu(fmaf(Jhi, wj1.x, ah1.x + bb1.x)),
                                 frelu(fmaf(Jhi, wj1.y, ah1.y + bb1.y)));

#pragma unroll
            for (int nt = 0; nt < 8; nt++) {
                const int n = nt * 8 + g;
                const unsigned b0 = *reinterpret_cast<const unsigned*>(&sW2[n * 72 + kt * 16 + 2 * q]);
                const unsigned b1 = *reinterpret_cast<const unsigned*>(&sW2[n * 72 + kt * 16 + 2 * q + 8]);
                mma16816(C1[nt], a0, a1, a2, a3, b0, b1);
            }
        }

        // ---------------- bias + relu + repack C1 -> stage-2 A fragments
        unsigned A2[4][4];
#pragma unroll
        for (int nt = 0; nt < 8; nt++) {
            const float2 bias = *reinterpret_cast<const float2*>(&sb2[nt * 8 + 2 * q]);
            const float e0 = frelu(C1[nt][0] + bias.x);
            const float e1 = frelu(C1[nt][1] + bias.y);
            const float e2 = frelu(C1[nt][2] + bias.x);
            const float e3 = frelu(C1[nt][3] + bias.y);
            const int kt2 = nt >> 1;
            if ((nt & 1) == 0) { A2[kt2][0] = packbf(e0, e1); A2[kt2][1] = packbf(e2, e3); }
            else               { A2[kt2][2] = packbf(e0, e1); A2[kt2][3] = packbf(e2, e3); }
        }

        // ---------------- stage 2: msg = m2 @ W3^T
        float C2[4][4];
#pragma unroll
        for (int nt = 0; nt < 4; nt++)
#pragma unroll
            for (int r = 0; r < 4; r++) C2[nt][r] = 0.f;

#pragma unroll
        for (int kt = 0; kt < 4; kt++) {
#pragma unroll
            for (int nt = 0; nt < 4; nt++) {
                const int n = nt * 8 + g;
                const unsigned b0 = *reinterpret_cast<const unsigned*>(&sW3[n * 72 + kt * 16 + 2 * q]);
                const unsigned b1 = *reinterpret_cast<const unsigned*>(&sW3[n * 72 + kt * 16 + 2 * q + 8]);
                mma16816(C2[nt], A2[kt][0], A2[kt][1], A2[kt][2], A2[kt][3], b0, b1);
            }
        }

        // ---------------- epilogue: relu(+b3), reduce over warp's 16 i-rows
#pragma unroll
        for (int nt = 0; nt < 4; nt++) {
            const float2 bias = *reinterpret_cast<const float2*>(&sb3[nt * 8 + 2 * q]);
            float s0 = frelu(C2[nt][0] + bias.x) + frelu(C2[nt][2] + bias.x);
            float s1 = frelu(C2[nt][1] + bias.y) + frelu(C2[nt][3] + bias.y);
#pragma unroll
            for (int m = 4; m < 32; m <<= 1) {
                s0 += __shfl_xor_sync(0xffffffffu, s0, m);
                s1 += __shfl_xor_sync(0xffffffffu, s1, m);
            }
            if (g == 0) {
                atomicAdd(&g_msg[(j0 + jl) * SD + nt * 8 + 2 * q],     s0);
                atomicAdd(&g_msg[(j0 + jl) * SD + nt * 8 + 2 * q + 1], s1);
            }
        }
    }
}

// ------------------------------------------------------ GRU phase (shared by fused kernels)
// warp w handles d = w, w+8, w+16, w+24 (weight rows warp-uniform => broadcast LDG),
// lane = node within the block's 32-node tile. Writes h_new into shn.
__device__ __forceinline__ void gru_phase(
    const float* __restrict__ sh, const float* __restrict__ smv, float* __restrict__ shn,
    const float* __restrict__ Wih, const float* __restrict__ Whh,
    const float* __restrict__ bih, const float* __restrict__ bhh,
    int w, int lane)
{
    for (int kq = 0; kq < 4; kq++) {
        const int d = w + 8 * kq;
        const float* Wr = Wih + d * 64;
        const float* Wz = Wih + (32 + d) * 64;
        const float* Wn = Wih + (64 + d) * 64;
        const float* Vr = Whh + d * 32;
        const float* Vz = Whh + (32 + d) * 32;
        const float* Vn = Whh + (64 + d) * 32;
        float ir = bih[d], iz = bih[32 + d], inn = bih[64 + d];
        float hr = bhh[d], hz = bhh[32 + d], hn = bhh[64 + d];
#pragma unroll 8
        for (int c = 0; c < 32; c++) {
            float hv = sh[lane * 33 + c], mv = smv[lane * 33 + c];
            ir  += Wr[c] * hv; ir  += Wr[32 + c] * mv;
            iz  += Wz[c] * hv; iz  += Wz[32 + c] * mv;
            inn += Wn[c] * hv; inn += Wn[32 + c] * mv;
            hr += Vr[c] * hv; hz += Vz[c] * hv; hn += Vn[c] * hv;
        }
        float r = 1.f / (1.f + expf(-(ir + hr)));
        float z = 1.f / (1.f + expf(-(iz + hz)));
        float n = tanhf(inn + r * hn);
        shn[lane * 33 + d] = (1.f - z) * n + z * sh[lane * 33 + d];
    }
}

// ----------------------------------------------- fused GRU + next-step prep
// grid 16 x 256: block owns nodes [n0, n0+32). Updates h in place, zeroes g_msg,
// then computes A/B for its nodes from smem h_new (W1 staged, stride-69 pad).
__global__ void __launch_bounds__(256) gru_prep_kernel(
    float* __restrict__ h, const float* __restrict__ bvec,
    const float* __restrict__ Wih, const float* __restrict__ Whh,
    const float* __restrict__ bih, const float* __restrict__ bhh,
    const float* __restrict__ mp_W1, const float* __restrict__ mp_b1)
{
    __shared__ float sh[32 * 33], smv[32 * 33], shn[32 * 33];
    __shared__ float sW1[64 * 69];   // 67 entries per row, stride 69 (conflict-free)
    const int t = threadIdx.x, w = t >> 5, lane = t & 31;
    const int n0 = blockIdx.x * 32;

    for (int idx = t; idx < 1024; idx += 256) {
        int r = idx >> 5, c = idx & 31;
        sh[r * 33 + c]  = h[(n0 + r) * SD + c];
        smv[r * 33 + c] = g_msg[(n0 + r) * SD + c];
        g_msg[(n0 + r) * SD + c] = 0.f;
    }
    for (int idx = t; idx < 64 * 67; idx += 256)
        sW1[(idx / 67) * 69 + (idx % 67)] = mp_W1[idx];
    __syncthreads();

    gru_phase(sh, smv, shn, Wih, Whh, bih, bhh, w, lane);
    __syncthreads();

    // write h_new back; then prep A/B for these 32 nodes
    for (int idx = t; idx < 1024; idx += 256) {
        int r = idx >> 5, c = idx & 31;
        h[(n0 + r) * SD + c] = shn[r * 33 + c];
    }

    const int kk = t & 63, ig = t >> 6;      // thread: k-column kk, i-rows ig*8..+8
    const float* row = &sW1[kk * 69];
    const float w65 = row[65], w66 = row[66], b1k = mp_b1[kk];
#pragma unroll
    for (int ii = 0; ii < 8; ii++) {
        const int i = ig * 8 + ii;
        float a = 0.f, bb = b1k;
#pragma unroll
        for (int dd = 0; dd < 32; dd++) {
            float hv = shn[i * 33 + dd];
            a += row[dd] * hv; bb += row[32 + dd] * hv;
        }
        const float bi = bvec[n0 + i];
        g_A[(n0 + i) * HM + kk] = a + bi * w65;
        g_B[(n0 + i) * HM + kk] = bb + bi * w66;
    }
}

// ----------------------------------------------- fused final GRU + readout
__global__ void __launch_bounds__(256) gru_read_kernel(
    const float* __restrict__ h,
    const float* __restrict__ Wih, const float* __restrict__ Whh,
    const float* __restrict__ bih, const float* __restrict__ bhh,
    const float* __restrict__ W1, const float* __restrict__ b1,
    const float* __restrict__ W2, const float* __restrict__ b2,
    const float* __restrict__ W3, const float* __restrict__ b3,
    float* __restrict__ out)
{
    __shared__ float sh[32 * 33], smv[32 * 33], shn[32 * 33];
    __shared__ float sy1[64 * 33], sy2[64 * 33];
    const int t = threadIdx.x, w = t >> 5, lane = t & 31;
    const int n0 = blockIdx.x * 32;

    for (int idx = t; idx < 1024; idx += 256) {
        int r = idx >> 5, c = idx & 31;
        sh[r * 33 + c]  = h[(n0 + r) * SD + c];
        smv[r * 33 + c] = g_msg[(n0 + r) * SD + c];
    }
    __syncthreads();

    gru_phase(sh, smv, shn, Wih, Whh, bih, bhh, w, lane);
    __syncthreads();

    for (int k = w; k < 64; k += 8) {
        float acc = b1[k];
        const float* Wrow = W1 + k * 32;
#pragma unroll
        for (int c = 0; c < 32; c++) acc += Wrow[c] * shn[lane * 33 + c];
        sy1[k * 33 + lane] = fmaxf(acc, 0.f);
    }
    __syncthreads();
    for (int k = w; k < 64; k += 8) {
        float acc = b2[k];
        const float* Wrow = W2 + k * 64;
#pragma unroll
        for (int c = 0; c < 64; c++) acc += Wrow[c] * sy1[c * 33 + lane];
        sy2[k * 33 + lane] = fmaxf(acc, 0.f);
    }
    __syncthreads();
    if (w < 2) {
        float acc = b3[w];
        const float* Wrow = W3 + w * 64;
#pragma unroll
        for (int c = 0; c < 64; c++) acc += Wrow[c] * sy2[c * 33 + lane];
        float y = fmaxf(acc, 0.f);
        out[(n0 + lane) * 2 + w] = 1.f / (1.f + expf(-y));
    }
}

extern "C" void kernel_launch(void* const* d_in, const int* in_sizes, int n_in,
                              void* d_out, int out_size)
{
    const float* J      = (const float*)d_in[0];
    const float* b      = (const float*)d_in[1];
    const float* mp_W1  = (const float*)d_in[2];
    const float* mp_b1  = (const float*)d_in[3];
    const float* mp_W2  = (const float*)d_in[4];
    const float* mp_b2  = (const float*)d_in[5];
    const float* mp_W3  = (const float*)d_in[6];
    const float* mp_b3  = (const float*)d_in[7];
    const float* Wih    = (const float*)d_in[8];
    const float* Whh    = (const float*)d_in[9];
    const float* bih    = (const float*)d_in[10];
    const float* bhh    = (const float*)d_in[11];
    const float* rW1    = (const float*)d_in[12];
    const float* rb1    = (const float*)d_in[13];
    const float* rW2    = (const float*)d_in[14];
    const float* rb2    = (const float*)d_in[15];
    const float* rW3    = (const float*)d_in[16];
    const float* rb3    = (const float*)d_in[17];
    float* out = (float*)d_out;

    float* p_h = nullptr;
    cudaGetSymbolAddress((void**)&p_h, g_h);

    init_kernel<<<64, 256>>>();
    prep_kernel<<<NND, 64>>>(p_h, b, mp_W1, mp_b1);   // h = 0 prep + msg zero

    dim3 g2(NND / (TJS * NSUB), NND / TI);   // (16, 16) blocks, 8 subtiles each
    for (int s = 0; s < 5; s++) {
        pair_mma_kernel<<<g2, 256>>>(J, mp_W1, mp_W2, mp_b2, mp_W3, mp_b3);
        if (s < 4)
            gru_prep_kernel<<<16, 256>>>(p_h, b, Wih, Whh, bih, bhh, mp_W1, mp_b1);
    }
    gru_read_kernel<<<16, 256>>>(p_h, Wih, Whh, bih, bhh,
                                 rW1, rb1, rW2, rb2, rW3, rb3, out);
}

// round 10
// speedup vs baseline: 1.1766x; 1.1766x over previous
#include <cuda_runtime.h>
#include <cuda_bf16.h>
#include <math.h>

#define NND 512
#define SD  32
#define HM  64
#define TI  32    // i-rows per block
#define TJS 4     // j-cols per subtile
#define NSUB 8    // subtiles per block (block covers 32 j total)

// Scratch (device globals: no allocation allowed)
__device__ float g_A[NND * HM];     // row term  (incl. b_i*wbi)
__device__ float g_B[NND * HM];     // col term  (incl. b_j*wbj + mp_b1)
__device__ float g_msg[NND * SD];   // msg_sum
__device__ float g_h[NND * SD];     // node state (in place; blocks own disjoint nodes)

__device__ __forceinline__ float frelu(float x) { return fmaxf(x, 0.f); }

__device__ __forceinline__ unsigned packbf(float lo, float hi) {
    __nv_bfloat162 h = __floats2bfloat162_rn(lo, hi);
    return *reinterpret_cast<unsigned*>(&h);
}

__device__ __forceinline__ void mma16816(float c[4],
                                         unsigned a0, unsigned a1, unsigned a2, unsigned a3,
                                         unsigned b0, unsigned b1) {
    asm volatile(
        "mma.sync.aligned.m16n8k16.row.col.f32.bf16.bf16.f32 "
        "{%0,%1,%2,%3}, {%4,%5,%6,%7}, {%8,%9}, {%0,%1,%2,%3};"
        : "+f"(c[0]), "+f"(c[1]), "+f"(c[2]), "+f"(c[3])
        : "r"(a0), "r"(a1), "r"(a2), "r"(a3), "r"(b0), "r"(b1));
}

// ---------------------------------------------------------------- init h = 0
__global__ void init_kernel() {
    int idx = blockIdx.x * 256 + threadIdx.x;
    if (idx < NND * SD) g_h[idx] = 0.f;
}

// ------------------------------------------------- step-0 rank-term prep (h = 0 state)
__global__ void __launch_bounds__(64) prep_kernel(
    const float* __restrict__ hin, const float* __restrict__ b,
    const float* __restrict__ mp_W1, const float* __restrict__ mp_b1)
{
    __shared__ float sh[SD];
    const int i = blockIdx.x, t = threadIdx.x;
    if (t < SD) { sh[t] = hin[i * SD + t]; g_msg[i * SD + t] = 0.f; }
    __syncthreads();
    const float* row = mp_W1 + t * 67;
    float a = 0.f, bb = mp_b1[t];
#pragma unroll
    for (int d = 0; d < SD; d++) { a += row[d] * sh[d]; bb += row[32 + d] * sh[d]; }
    const float bi = b[i];
    g_A[i * HM + t] = a + bi * row[65];
    g_B[i * HM + t] = bb + bi * row[66];
}

// ---------------------------------------------------- pairwise message MLP (tensor cores)
// (UNCHANGED from the NSUB=8 version)
__global__ void __launch_bounds__(256) pair_mma_kernel(
    const float* __restrict__ J, const float* __restrict__ mp_W1,
    const float* __restrict__ W2, const float* __restrict__ b2,
    const float* __restrict__ W3, const float* __restrict__ b3)
{
    __shared__ __nv_bfloat16 sW2[HM * 72];
    __shared__ __nv_bfloat16 sW3[SD * 72];
    __shared__ float sA[TI * 72];
    __shared__ float sB[TJS * HM];
    __shared__ float swJ[HM], sb2[HM], sb3[SD];

    const int t = threadIdx.x, w = t >> 5, l = t & 31;
    const int jbase = blockIdx.x * (TJS * NSUB), i0 = blockIdx.y * TI;

    for (int idx = t; idx < HM * HM; idx += 256)
        sW2[(idx >> 6) * 72 + (idx & 63)] = __float2bfloat16(W2[idx]);
    for (int idx = t; idx < SD * HM; idx += 256)
        sW3[(idx >> 6) * 72 + (idx & 63)] = __float2bfloat16(W3[idx]);
    for (int idx = t; idx < TI * HM; idx += 256)
        sA[(idx >> 6) * 72 + (idx & 63)] = g_A[(i0 + (idx >> 6)) * HM + (idx & 63)];
    if (t < HM) { swJ[t] = mp_W1[t * 67 + 64]; sb2[t] = b2[t]; }
    if (t < SD) sb3[t] = b3[t];

    const int jl = w >> 1;
    const int g = l >> 2, q = l & 3;
    const int ilo = (w & 1) * 16 + g;
    const int ihi = ilo + 8;

    for (int sub = 0; sub < NSUB; sub++) {
        const int j0 = jbase + sub * TJS;
        __syncthreads();
        for (int idx = t; idx < TJS * HM; idx += 256)
            sB[idx] = g_B[(j0 + (idx >> 6)) * HM + (idx & 63)];
        __syncthreads();

        const float Jlo = J[(i0 + ilo) * NND + (j0 + jl)];
        const float Jhi = J[(i0 + ihi) * NND + (j0 + jl)];

        float C1[8][4];
#pragma unroll
        for (int nt = 0; nt < 8; nt++)
#pragma unroll
            for (int r = 0; r < 4; r++) C1[nt][r] = 0.f;

#pragma unroll
        for (int kt = 0; kt < 4; kt++) {
            const int c0 = kt * 16 + 2 * q;
            const float2 wj0 = *reinterpret_cast<const float2*>(&swJ[c0]);
            const float2 wj1 = *reinterpret_cast<const float2*>(&swJ[c0 + 8]);
            const float2 al0 = *reinterpret_cast<const float2*>(&sA[ilo * 72 + c0]);
            const float2 al1 = *reinterpret_cast<const float2*>(&sA[ilo * 72 + c0 + 8]);
            const float2 ah0 = *reinterpret_cast<const float2*>(&sA[ihi * 72 + c0]);
            const float2 ah1 = *reinterpret_cast<const float2*>(&sA[ihi * 72 + c0 + 8]);
            const float2 bb0 = *reinterpret_cast<const float2*>(&sB[jl * HM + c0]);
            const float2 bb1 = *reinterpret_cast<const float2*>(&sB[jl * HM + c0 + 8]);

            unsigned a0 = packbf(frelu(fmaf(Jlo, wj0.x, al0.x + bb0.x)),
                                 frelu(fmaf(Jlo, wj0.y, al0.y + bb0.y)));
            unsigned a1 = packbf(frelu(fmaf(Jhi, wj0.x, ah0.x + bb0.x)),
                                 frelu(fmaf(Jhi, wj0.y, ah0.y + bb0.y)));
            unsigned a2 = packbf(frelu(fmaf(Jlo, wj1.x, al1.x + bb1.x)),
                                 frelu(fmaf(Jlo, wj1.y, al1.y + bb1.y)));
            unsigned a3 = packbf(frelu(fmaf(Jhi, wj1.x, ah1.x + bb1.x)),
                                 frelu(fmaf(Jhi, wj1.y, ah1.y + bb1.y)));

#pragma unroll
            for (int nt = 0; nt < 8; nt++) {
                const int n = nt * 8 + g;
                const unsigned b0 = *reinterpret_cast<const unsigned*>(&sW2[n * 72 + kt * 16 + 2 * q]);
                const unsigned b1 = *reinterpret_cast<const unsigned*>(&sW2[n * 72 + kt * 16 + 2 * q + 8]);
                mma16816(C1[nt], a0, a1, a2, a3, b0, b1);
            }
        }

        unsigned A2[4][4];
#pragma unroll
        for (int nt = 0; nt < 8; nt++) {
            const float2 bias = *reinterpret_cast<const float2*>(&sb2[nt * 8 + 2 * q]);
            const float e0 = frelu(C1[nt][0] + bias.x);
            const float e1 = frelu(C1[nt][1] + bias.y);
            const float e2 = frelu(C1[nt][2] + bias.x);
            const float e3 = frelu(C1[nt][3] + bias.y);
            const int kt2 = nt >> 1;
            if ((nt & 1) == 0) { A2[kt2][0] = packbf(e0, e1); A2[kt2][1] = packbf(e2, e3); }
            else               { A2[kt2][2] = packbf(e0, e1); A2[kt2][3] = packbf(e2, e3); }
        }

        float C2[4][4];
#pragma unroll
        for (int nt = 0; nt < 4; nt++)
#pragma unroll
            for (int r = 0; r < 4; r++) C2[nt][r] = 0.f;

#pragma unroll
        for (int kt = 0; kt < 4; kt++) {
#pragma unroll
            for (int nt = 0; nt < 4; nt++) {
                const int n = nt * 8 + g;
                const unsigned b0 = *reinterpret_cast<const unsigned*>(&sW3[n * 72 + kt * 16 + 2 * q]);
                const unsigned b1 = *reinterpret_cast<const unsigned*>(&sW3[n * 72 + kt * 16 + 2 * q + 8]);
                mma16816(C2[nt], A2[kt][0], A2[kt][1], A2[kt][2], A2[kt][3], b0, b1);
            }
        }

#pragma unroll
        for (int nt = 0; nt < 4; nt++) {
            const float2 bias = *reinterpret_cast<const float2*>(&sb3[nt * 8 + 2 * q]);
            float s0 = frelu(C2[nt][0] + bias.x) + frelu(C2[nt][2] + bias.x);
            float s1 = frelu(C2[nt][1] + bias.y) + frelu(C2[nt][3] + bias.y);
#pragma unroll
            for (int m = 4; m < 32; m <<= 1) {
                s0 += __shfl_xor_sync(0xffffffffu, s0, m);
                s1 += __shfl_xor_sync(0xffffffffu, s1, m);
            }
            if (g == 0) {
                atomicAdd(&g_msg[(j0 + jl) * SD + nt * 8 + 2 * q],     s0);
                atomicAdd(&g_msg[(j0 + jl) * SD + nt * 8 + 2 * q + 1], s1);
            }
        }
    }
}

// ------------------------------------------------------ GRU phase, thread = (node, d)
// Weights pre-staged in smem with odd strides (65 / 33): every lane pattern is
// conflict-free (d varies across lanes, stride odd => distinct banks).
__device__ __forceinline__ void gru_phase8(
    const float* __restrict__ sh, const float* __restrict__ smv, float* __restrict__ shn,
    const float* __restrict__ sWih, const float* __restrict__ sWhh,
    const float* __restrict__ bih, const float* __restrict__ bhh, int n, int d)
{
    const float* Wr = sWih + d * 65;
    const float* Wz = sWih + (32 + d) * 65;
    const float* Wn = sWih + (64 + d) * 65;
    const float* Vr = sWhh + d * 33;
    const float* Vz = sWhh + (32 + d) * 33;
    const float* Vn = sWhh + (64 + d) * 33;
    float ir = bih[d], iz = bih[32 + d], inn = bih[64 + d];
    float hr = bhh[d], hz = bhh[32 + d], hn = bhh[64 + d];
#pragma unroll 8
    for (int c = 0; c < 32; c++) {
        float hv = sh[n * 33 + c], mv = smv[n * 33 + c];
        ir  += Wr[c] * hv; ir  += Wr[32 + c] * mv;
        iz  += Wz[c] * hv; iz  += Wz[32 + c] * mv;
        inn += Wn[c] * hv; inn += Wn[32 + c] * mv;
        hr += Vr[c] * hv; hz += Vz[c] * hv; hn += Vn[c] * hv;
    }
    float r = 1.f / (1.f + expf(-(ir + hr)));
    float z = 1.f / (1.f + expf(-(iz + hz)));
    float ng = tanhf(inn + r * hn);
    shn[n * 33 + d] = (1.f - z) * ng + z * sh[n * 33 + d];
}

// ----------------------------------------------- fused GRU + next-step prep
// grid 64 x 256 threads: block owns nodes [8b, 8b+8). Thread = (node, d) for GRU;
// thread = (k-column, node-pair) for prep. All weights staged to padded smem.
#define GP_SH   0
#define GP_SMV  264
#define GP_SHN  528
#define GP_WIH  792     // 96 x 65
#define GP_WHH  7032    // 96 x 33
#define GP_W1   10200   // 64 x 69
#define GP_FLOATS 14616
__global__ void __launch_bounds__(256) gru_prep_kernel(
    float* __restrict__ h, const float* __restrict__ bvec,
    const float* __restrict__ Wih, const float* __restrict__ Whh,
    const float* __restrict__ bih, const float* __restrict__ bhh,
    const float* __restrict__ mp_W1, const float* __restrict__ mp_b1)
{
    extern __shared__ float sm[];
    const int t = threadIdx.x;
    const int n0 = blockIdx.x * 8;
    const int n = t >> 5, d = t & 31;

    {   // h/msg: exactly one element per thread
        sm[GP_SH  + n * 33 + d] = h[(n0 + n) * SD + d];
        sm[GP_SMV + n * 33 + d] = g_msg[(n0 + n) * SD + d];
        g_msg[(n0 + n) * SD + d] = 0.f;
    }
    for (int idx = t; idx < 96 * 64; idx += 256)
        sm[GP_WIH + (idx >> 6) * 65 + (idx & 63)] = Wih[idx];
    for (int idx = t; idx < 96 * 32; idx += 256)
        sm[GP_WHH + (idx >> 5) * 33 + (idx & 31)] = Whh[idx];
    for (int idx = t; idx < 64 * 67; idx += 256)
        sm[GP_W1 + (idx / 67) * 69 + (idx % 67)] = mp_W1[idx];
    __syncthreads();

    gru_phase8(sm + GP_SH, sm + GP_SMV, sm + GP_SHN,
               sm + GP_WIH, sm + GP_WHH, bih, bhh, n, d);
    __syncthreads();

    // write h_new back (own element), then prep A/B for these 8 nodes
    h[(n0 + n) * SD + d] = sm[GP_SHN + n * 33 + d];

    const int kk = t & 63, ig = t >> 6;      // k-column, node-pair group
    const float* row = &sm[GP_W1 + kk * 69];
    const float w65 = row[65], w66 = row[66], b1k = mp_b1[kk];
#pragma unroll
    for (int ii = 0; ii < 2; ii++) {
        const int i = ig * 2 + ii;
        float a = 0.f, bb = b1k;
#pragma unroll
        for (int dd = 0; dd < 32; dd++) {
            float hv = sm[GP_SHN + i * 33 + dd];
            a += row[dd] * hv; bb += row[32 + dd] * hv;
        }
        const float bi = bvec[n0 + i];
        g_A[(n0 + i) * HM + kk] = a + bi * w65;
        g_B[(n0 + i) * HM + kk] = bb + bi * w66;
    }
}

// ----------------------------------------------- fused final GRU + readout
#define GR_SH   0
#define GR_SMV  264
#define GR_SHN  528
#define GR_WIH  792     // 96 x 65
#define GR_WHH  7032    // 96 x 33
#define GR_RW1  10200   // 64 x 33
#define GR_RW2  12312   // 64 x 65
#define GR_SY1  16472   // 8 x 65
#define GR_SY2  16992   // 8 x 65
#define GR_FLOATS 17512
__global__ void __launch_bounds__(256) gru_read_kernel(
    const float* __restrict__ h,
    const float* __restrict__ Wih, const float* __restrict__ Whh,
    const float* __restrict__ bih, const float* __restrict__ bhh,
    const float* __restrict__ W1, const float* __restrict__ b1,
    const float* __restrict__ W2, const float* __restrict__ b2,
    const float* __restrict__ W3, const float* __restrict__ b3,
    float* __restrict__ out)
{
    extern __shared__ float sm[];
    const int t = threadIdx.x;
    const int n0 = blockIdx.x * 8;
    const int n = t >> 5, d = t & 31;

    sm[GR_SH  + n * 33 + d] = h[(n0 + n) * SD + d];
    sm[GR_SMV + n * 33 + d] = g_msg[(n0 + n) * SD + d];
    for (int idx = t; idx < 96 * 64; idx += 256)
        sm[GR_WIH + (idx >> 6) * 65 + (idx & 63)] = Wih[idx];
    for (int idx = t; idx < 96 * 32; idx += 256)
        sm[GR_WHH + (idx >> 5) * 33 + (idx & 31)] = Whh[idx];
    for (int idx = t; idx < 64 * 32; idx += 256)
        sm[GR_RW1 + (idx >> 5) * 33 + (idx & 31)] = W1[idx];
    for (int idx = t; idx < 64 * 64; idx += 256)
        sm[GR_RW2 + (idx >> 6) * 65 + (idx & 63)] = W2[idx];
    __syncthreads();

    gru_phase8(sm + GR_SH, sm + GR_SMV, sm + GR_SHN,
               sm + GR_WIH, sm + GR_WHH, bih, bhh, n, d);
    __syncthreads();

    const int kk = t & 63, ig = t >> 6;
    // y1 = relu(h_new @ rW1^T + b1)
    {
        const float* row = &sm[GR_RW1 + kk * 33];
        const float b1k = b1[kk];
#pragma unroll
        for (int ii = 0; ii < 2; ii++) {
            const int i = ig * 2 + ii;
            float acc = b1k;
#pragma unroll
            for (int c = 0; c < 32; c++) acc += row[c] * sm[GR_SHN + i * 33 + c];
            sm[GR_SY1 + i * 65 + kk] = frelu(acc);
        }
    }
    __syncthreads();
    // y2 = relu(y1 @ rW2^T + b2)
    {
        const float* row = &sm[GR_RW2 + kk * 65];
        const float b2k = b2[kk];
#pragma unroll
        for (int ii = 0; ii < 2; ii++) {
            const int i = ig * 2 + ii;
            float acc = b2k;
#pragma unroll
            for (int c = 0; c < 64; c++) acc += row[c] * sm[GR_SY1 + i * 65 + c];
            sm[GR_SY2 + i * 65 + kk] = frelu(acc);
        }
    }
    __syncthreads();
    // y3 = sigmoid(relu(y2 @ rW3^T + b3))
    if (t < 16) {
        const int i = t >> 1, o = t & 1;
        float acc = b3[o];
        const float* row = W3 + o * 64;
#pragma unroll
        for (int c = 0; c < 64; c++) acc += row[c] * sm[GR_SY2 + i * 65 + c];
        float y = frelu(acc);
        out[(n0 + i) * 2 + o] = 1.f / (1.f + expf(-y));
    }
}

extern "C" void kernel_launch(void* const* d_in, const int* in_sizes, int n_in,
                              void* d_out, int out_size)
{
    const float* J      = (const float*)d_in[0];
    const float* b      = (const float*)d_in[1];
    const float* mp_W1  = (const float*)d_in[2];
    const float* mp_b1  = (const float*)d_in[3];
    const float* mp_W2  = (const float*)d_in[4];
    const float* mp_b2  = (const float*)d_in[5];
    const float* mp_W3  = (const float*)d_in[6];
    const float* mp_b3  = (const float*)d_in[7];
    const float* Wih    = (const float*)d_in[8];
    const float* Whh    = (const float*)d_in[9];
    const float* bih    = (const float*)d_in[10];
    const float* bhh    = (const float*)d_in[11];
    const float* rW1    = (const float*)d_in[12];
    const float* rb1    = (const float*)d_in[13];
    const float* rW2    = (const float*)d_in[14];
    const float* rb2    = (const float*)d_in[15];
    const float* rW3    = (const float*)d_in[16];
    const float* rb3    = (const float*)d_in[17];
    float* out = (float*)d_out;

    float* p_h = nullptr;
    cudaGetSymbolAddress((void**)&p_h, g_h);

    static bool attr_done = false;
    if (!attr_done) {
        cudaFuncSetAttribute(gru_prep_kernel, cudaFuncAttributeMaxDynamicSharedMemorySize,
                             GP_FLOATS * 4);
        cudaFuncSetAttribute(gru_read_kernel, cudaFuncAttributeMaxDynamicSharedMemorySize,
                             GR_FLOATS * 4);
        attr_done = true;
    }

    init_kernel<<<64, 256>>>();
    prep_kernel<<<NND, 64>>>(p_h, b, mp_W1, mp_b1);   // h = 0 prep + msg zero

    dim3 g2(NND / (TJS * NSUB), NND / TI);   // (16, 16) blocks, 8 subtiles each
    for (int s = 0; s < 5; s++) {
        pair_mma_kernel<<<g2, 256>>>(J, mp_W1, mp_W2, mp_b2, mp_W3, mp_b3);
        if (s < 4)
            gru_prep_kernel<<<64, 256, GP_FLOATS * 4>>>(p_h, b, Wih, Whh, bih, bhh,
                                                        mp_W1, mp_b1);
    }
    gru_read_kernel<<<64, 256, GR_FLOATS * 4>>>(p_h, Wih, Whh, bih, bhh,
                                                rW1, rb1, rW2, rb2, rW3, rb3, out);
}

// round 11
// speedup vs baseline: 1.1864x; 1.0083x over previous
#include <cuda_runtime.h>
#include <cuda_bf16.h>
#include <math.h>

#define NND 512
#define SD  32
#define HM  64
#define TI  32    // i-rows per block
#define TJS 4     // j-cols per subtile
#define NSUB 8    // subtiles per block (block covers 32 j total)

// Scratch (device globals: no allocation allowed)
__device__ float g_A[NND * HM];     // row term  (incl. b_i*wbi)
__device__ float g_B[NND * HM];     // col term  (incl. b_j*wbj + mp_b1)
__device__ float g_msg[NND * SD];   // msg_sum
__device__ float g_h0[NND * SD];
__device__ float g_h1[NND * SD];

__device__ __forceinline__ float frelu(float x) { return fmaxf(x, 0.f); }

__device__ __forceinline__ unsigned packbf(float lo, float hi) {
    __nv_bfloat162 h = __floats2bfloat162_rn(lo, hi);
    return *reinterpret_cast<unsigned*>(&h);
}

__device__ __forceinline__ void mma16816(float c[4],
                                         unsigned a0, unsigned a1, unsigned a2, unsigned a3,
                                         unsigned b0, unsigned b1) {
    asm volatile(
        "mma.sync.aligned.m16n8k16.row.col.f32.bf16.bf16.f32 "
        "{%0,%1,%2,%3}, {%4,%5,%6,%7}, {%8,%9}, {%0,%1,%2,%3};"
        : "+f"(c[0]), "+f"(c[1]), "+f"(c[2]), "+f"(c[3])
        : "r"(a0), "r"(a1), "r"(a2), "r"(a3), "r"(b0), "r"(b1));
}

// ---------------------------------------------------------------- init h = 0
__global__ void init_kernel() {
    int idx = blockIdx.x * 256 + threadIdx.x;
    if (idx < NND * SD) g_h0[idx] = 0.f;
}

// ------------------------------------------------- per-step rank-term prep
// A[i][k] = sum_d h[i][d]*W1[k][d]      + b[i]*W1[k][65]
// B[i][k] = sum_d h[i][d]*W1[k][32+d]   + b[i]*W1[k][66] + mp_b1[k]
__global__ void __launch_bounds__(64) prep_kernel(
    const float* __restrict__ hin, const float* __restrict__ b,
    const float* __restrict__ mp_W1, const float* __restrict__ mp_b1)
{
    __shared__ float sh[SD];
    const int i = blockIdx.x, t = threadIdx.x;
    if (t < SD) { sh[t] = hin[i * SD + t]; g_msg[i * SD + t] = 0.f; }
    __syncthreads();
    const float* row = mp_W1 + t * 67;
    float a = 0.f, bb = mp_b1[t];
#pragma unroll
    for (int d = 0; d < SD; d++) { a += row[d] * sh[d]; bb += row[32 + d] * sh[d]; }
    const float bi = b[i];
    g_A[i * HM + t] = a + bi * row[65];
    g_B[i * HM + t] = bb + bi * row[66];
}

// ---------------------------------------------------- pairwise message MLP (tensor cores)
// Block: 256 threads, covers 32 i-rows x 32 j-cols as 8 sequential subtiles of
// 32x4 (=128 pairs). Per subtile: warp w -> j_local = w>>1, rows (w&1)*16 .. +16.
// W2/W3/A/biases staged once per block; only B + J are per-subtile.
__global__ void __launch_bounds__(256) pair_mma_kernel(
    const float* __restrict__ J, const float* __restrict__ mp_W1,
    const float* __restrict__ W2, const float* __restrict__ b2,
    const float* __restrict__ W3, const float* __restrict__ b3)
{
    __shared__ __nv_bfloat16 sW2[HM * 72];
    __shared__ __nv_bfloat16 sW3[SD * 72];
    __shared__ float sA[TI * 72];
    __shared__ float sB[TJS * HM];
    __shared__ float swJ[HM], sb2[HM], sb3[SD];

    const int t = threadIdx.x, w = t >> 5, l = t & 31;
    const int jbase = blockIdx.x * (TJS * NSUB), i0 = blockIdx.y * TI;

    for (int idx = t; idx < HM * HM; idx += 256)
        sW2[(idx >> 6) * 72 + (idx & 63)] = __float2bfloat16(W2[idx]);
    for (int idx = t; idx < SD * HM; idx += 256)
        sW3[(idx >> 6) * 72 + (idx & 63)] = __float2bfloat16(W3[idx]);
    for (int idx = t; idx < TI * HM; idx += 256)
        sA[(idx >> 6) * 72 + (idx & 63)] = g_A[(i0 + (idx >> 6)) * HM + (idx & 63)];
    if (t < HM) { swJ[t] = mp_W1[t * 67 + 64]; sb2[t] = b2[t]; }
    if (t < SD) sb3[t] = b3[t];

    const int jl = w >> 1;
    const int g = l >> 2, q = l & 3;
    const int ilo = (w & 1) * 16 + g;
    const int ihi = ilo + 8;

    for (int sub = 0; sub < NSUB; sub++) {
        const int j0 = jbase + sub * TJS;
        __syncthreads();
        for (int idx = t; idx < TJS * HM; idx += 256)
            sB[idx] = g_B[(j0 + (idx >> 6)) * HM + (idx & 63)];
        __syncthreads();

        const float Jlo = J[(i0 + ilo) * NND + (j0 + jl)];
        const float Jhi = J[(i0 + ihi) * NND + (j0 + jl)];

        float C1[8][4];
#pragma unroll
        for (int nt = 0; nt < 8; nt++)
#pragma unroll
            for (int r = 0; r < 4; r++) C1[nt][r] = 0.f;

        // ---------------- stage 1: m2 accum = m1 @ W2^T
#pragma unroll
        for (int kt = 0; kt < 4; kt++) {
            const int c0 = kt * 16 + 2 * q;
            const float2 wj0 = *reinterpret_cast<const float2*>(&swJ[c0]);
            const float2 wj1 = *reinterpret_cast<const float2*>(&swJ[c0 + 8]);
            const float2 al0 = *reinterpret_cast<const float2*>(&sA[ilo * 72 + c0]);
            const float2 al1 = *reinterpret_cast<const float2*>(&sA[ilo * 72 + c0 + 8]);
            const float2 ah0 = *reinterpret_cast<const float2*>(&sA[ihi * 72 + c0]);
            const float2 ah1 = *reinterpret_cast<const float2*>(&sA[ihi * 72 + c0 + 8]);
            const float2 bb0 = *reinterpret_cast<const float2*>(&sB[jl * HM + c0]);
            const float2 bb1 = *reinterpret_cast<const float2*>(&sB[jl * HM + c0 + 8]);

            unsigned a0 = packbf(frelu(fmaf(Jlo, wj0.x, al0.x + bb0.x)),
                                 frelu(fmaf(Jlo, wj0.y, al0.y + bb0.y)));
            unsigned a1 = packbf(frelu(fmaf(Jhi, wj0.x, ah0.x + bb0.x)),
                                 frelu(fmaf(Jhi, wj0.y, ah0.y + bb0.y)));
            unsigned a2 = packbf(frelu(fmaf(Jlo, wj1.x, al1.x + bb1.x)),
                                 frelu(fmaf(Jlo, wj1.y, al1.y + bb1.y)));
            unsigned a3 = packbf(frelu(fmaf(Jhi, wj1.x, ah1.x + bb1.x)),
                                 frelu(fmaf(Jhi, wj1.y, ah1.y + bb1.y)));

#pragma unroll
            for (int nt = 0; nt < 8; nt++) {
                const int n = nt * 8 + g;
                const unsigned b0 = *reinterpret_cast<const unsigned*>(&sW2[n * 72 + kt * 16 + 2 * q]);
                const unsigned b1 = *reinterpret_cast<const unsigned*>(&sW2[n * 72 + kt * 16 + 2 * q + 8]);
                mma16816(C1[nt], a0, a1, a2, a3, b0, b1);
            }
        }

        // ---------------- bias + relu + repack C1 -> stage-2 A fragments
        unsigned A2[4][4];
#pragma unroll
        for (int nt = 0; nt < 8; nt++) {
            const float2 bias = *reinterpret_cast<const float2*>(&sb2[nt * 8 + 2 * q]);
            const float e0 = frelu(C1[nt][0] + bias.x);
            const float e1 = frelu(C1[nt][1] + bias.y);
            const float e2 = frelu(C1[nt][2] + bias.x);
            const float e3 = frelu(C1[nt][3] + bias.y);
            const int kt2 = nt >> 1;
            if ((nt & 1) == 0) { A2[kt2][0] = packbf(e0, e1); A2[kt2][1] = packbf(e2, e3); }
            else               { A2[kt2][2] = packbf(e0, e1); A2[kt2][3] = packbf(e2, e3); }
        }

        // ---------------- stage 2: msg = m2 @ W3^T
        float C2[4][4];
#pragma unroll
        for (int nt = 0; nt < 4; nt++)
#pragma unroll
            for (int r = 0; r < 4; r++) C2[nt][r] = 0.f;

#pragma unroll
        for (int kt = 0; kt < 4; kt++) {
#pragma unroll
            for (int nt = 0; nt < 4; nt++) {
                const int n = nt * 8 + g;
                const unsigned b0 = *reinterpret_cast<const unsigned*>(&sW3[n * 72 + kt * 16 + 2 * q]);
                const unsigned b1 = *reinterpret_cast<const unsigned*>(&sW3[n * 72 + kt * 16 + 2 * q + 8]);
                mma16816(C2[nt], A2[kt][0], A2[kt][1], A2[kt][2], A2[kt][3], b0, b1);
            }
        }

        // ---------------- epilogue: relu(+b3), reduce over warp's 16 i-rows
#pragma unroll
        for (int nt = 0; nt < 4; nt++) {
            const float2 bias = *reinterpret_cast<const float2*>(&sb3[nt * 8 + 2 * q]);
            float s0 = frelu(C2[nt][0] + bias.x) + frelu(C2[nt][2] + bias.x);
            float s1 = frelu(C2[nt][1] + bias.y) + frelu(C2[nt][3] + bias.y);
#pragma unroll
            for (int m = 4; m < 32; m <<= 1) {
                s0 += __shfl_xor_sync(0xffffffffu, s0, m);
                s1 += __shfl_xor_sync(0xffffffffu, s1, m);
            }
            if (g == 0) {
                atomicAdd(&g_msg[(j0 + jl) * SD + nt * 8 + 2 * q],     s0);
                atomicAdd(&g_msg[(j0 + jl) * SD + nt * 8 + 2 * q + 1], s1);
            }
        }
    }
}

// ----------------------------------------------------------------- GRU step
// warp = one d (broadcast weight reads), lane = node within 32-node tile
__global__ void __launch_bounds__(256) gru_kernel(
    const float* __restrict__ hin, float* __restrict__ hout,
    const float* __restrict__ Wih, const float* __restrict__ Whh,
    const float* __restrict__ bih, const float* __restrict__ bhh)
{
    __shared__ float sh[32 * 33], sm[32 * 33];
    const int t = threadIdx.x, w = t >> 5, lane = t & 31;
    const int n0 = blockIdx.x * 32;
    const int d = blockIdx.y * 8 + w;
    for (int idx = t; idx < 1024; idx += 256) {
        int r = idx >> 5, c = idx & 31;
        sh[r * 33 + c] = hin[(n0 + r) * SD + c];
        sm[r * 33 + c] = g_msg[(n0 + r) * SD + c];
    }
    __syncthreads();
    const float* Wr = Wih + d * 64;
    const float* Wz = Wih + (32 + d) * 64;
    const float* Wn = Wih + (64 + d) * 64;
    const float* Vr = Whh + d * 32;
    const float* Vz = Whh + (32 + d) * 32;
    const float* Vn = Whh + (64 + d) * 32;
    float ir = bih[d], iz = bih[32 + d], inn = bih[64 + d];
    float hr = bhh[d], hz = bhh[32 + d], hn = bhh[64 + d];
#pragma unroll 8
    for (int c = 0; c < 32; c++) {
        float hv = sh[lane * 33 + c], mv = sm[lane * 33 + c];
        ir  += Wr[c] * hv; ir  += Wr[32 + c] * mv;
        iz  += Wz[c] * hv; iz  += Wz[32 + c] * mv;
        inn += Wn[c] * hv; inn += Wn[32 + c] * mv;
        hr += Vr[c] * hv; hz += Vz[c] * hv; hn += Vn[c] * hv;
    }
    float r = 1.f / (1.f + expf(-(ir + hr)));
    float z = 1.f / (1.f + expf(-(iz + hz)));
    float n = tanhf(inn + r * hn);
    hout[(n0 + lane) * SD + d] = (1.f - z) * n + z * sh[lane * 33 + d];
}

// ----------------------------------------------------------------- readout
__global__ void __launch_bounds__(256) readout_kernel(
    const float* __restrict__ h,
    const float* __restrict__ W1, const float* __restrict__ b1,
    const float* __restrict__ W2, const float* __restrict__ b2,
    const float* __restrict__ W3, const float* __restrict__ b3,
    float* __restrict__ out)
{
    __shared__ float sh[32 * 33];
    __shared__ float sy1[64 * 33];
    __shared__ float sy2[64 * 33];
    const int t = threadIdx.x, w = t >> 5, lane = t & 31;
    const int n0 = blockIdx.x * 32;
    for (int idx = t; idx < 1024; idx += 256) {
        int r = idx >> 5, c = idx & 31;
        sh[r * 33 + c] = h[(n0 + r) * SD + c];
    }
    __syncthreads();
    for (int k = w; k < 64; k += 8) {
        float acc = b1[k];
        const float* Wrow = W1 + k * 32;
#pragma unroll
        for (int c = 0; c < 32; c++) acc += Wrow[c] * sh[lane * 33 + c];
        sy1[k * 33 + lane] = fmaxf(acc, 0.f);
    }
    __syncthreads();
    for (int k = w; k < 64; k += 8) {
        float acc = b2[k];
        const float* Wrow = W2 + k * 64;
#pragma unroll
        for (int c = 0; c < 64; c++) acc += Wrow[c] * sy1[c * 33 + lane];
        sy2[k * 33 + lane] = fmaxf(acc, 0.f);
    }
    __syncthreads();
    if (w < 2) {
        float acc = b3[w];
        const float* Wrow = W3 + w * 64;
#pragma unroll
        for (int c = 0; c < 64; c++) acc += Wrow[c] * sy2[c * 33 + lane];
        float y = fmaxf(acc, 0.f);
        out[(n0 + lane) * 2 + w] = 1.f / (1.f + expf(-y));
    }
}

extern "C" void kernel_launch(void* const* d_in, const int* in_sizes, int n_in,
                              void* d_out, int out_size)
{
    const float* J      = (const float*)d_in[0];
    const float* b      = (const float*)d_in[1];
    const float* mp_W1  = (const float*)d_in[2];
    const float* mp_b1  = (const float*)d_in[3];
    const float* mp_W2  = (const float*)d_in[4];
    const float* mp_b2  = (const float*)d_in[5];
    const float* mp_W3  = (const float*)d_in[6];
    const float* mp_b3  = (const float*)d_in[7];
    const float* Wih    = (const float*)d_in[8];
    const float* Whh    = (const float*)d_in[9];
    const float* bih    = (const float*)d_in[10];
    const float* bhh    = (const float*)d_in[11];
    const float* rW1    = (const float*)d_in[12];
    const float* rb1    = (const float*)d_in[13];
    const float* rW2    = (const float*)d_in[14];
    const float* rb2    = (const float*)d_in[15];
    const float* rW3    = (const float*)d_in[16];
    const float* rb3    = (const float*)d_in[17];
    float* out = (float*)d_out;

    float *p_h0 = nullptr, *p_h1 = nullptr;
    cudaGetSymbolAddress((void**)&p_h0, g_h0);
    cudaGetSymbolAddress((void**)&p_h1, g_h1);

    init_kernel<<<64, 256>>>();

    float* hcur = p_h0;
    float* hnext = p_h1;
    for (int s = 0; s < 5; s++) {
        prep_kernel<<<NND, 64>>>(hcur, b, mp_W1, mp_b1);
        dim3 g2(NND / (TJS * NSUB), NND / TI);   // (16, 16) blocks, 8 subtiles each
        pair_mma_kernel<<<g2, 256>>>(J, mp_W1, mp_W2, mp_b2, mp_W3, mp_b3);
        gru_kernel<<<dim3(16, 4), 256>>>(hcur, hnext, Wih, Whh, bih, bhh);
        float* tmp = hcur; hcur = hnext; hnext = tmp;
    }
    readout_kernel<<<16, 256>>>(hcur, rW1, rb1, rW2, rb2, rW3, rb3, out);
}

// round 12
// speedup vs baseline: 1.2273x; 1.0345x over previous
#include <cuda_runtime.h>
#include <cuda_bf16.h>
#include <math.h>

#define NND 512
#define SD  32
#define HM  64
#define TI  32    // i-rows per block
#define TJS 4     // j-cols per subtile
#define NSUB 4    // subtiles per block (block covers 16 j total)

// Scratch (device globals: no allocation allowed)
__device__ float g_A[NND * HM];     // row term  (incl. b_i*wbi)
__device__ float g_B[NND * HM];     // col term  (incl. b_j*wbj + mp_b1)
__device__ float g_msg[NND * SD];   // msg_sum
__device__ float g_h0[NND * SD];
__device__ float g_h1[NND * SD];

__device__ __forceinline__ float frelu(float x) { return fmaxf(x, 0.f); }

__device__ __forceinline__ unsigned packbf(float lo, float hi) {
    __nv_bfloat162 h = __floats2bfloat162_rn(lo, hi);
    return *reinterpret_cast<unsigned*>(&h);
}

__device__ __forceinline__ void mma16816(float c[4],
                                         unsigned a0, unsigned a1, unsigned a2, unsigned a3,
                                         unsigned b0, unsigned b1) {
    asm volatile(
        "mma.sync.aligned.m16n8k16.row.col.f32.bf16.bf16.f32 "
        "{%0,%1,%2,%3}, {%4,%5,%6,%7}, {%8,%9}, {%0,%1,%2,%3};"
        : "+f"(c[0]), "+f"(c[1]), "+f"(c[2]), "+f"(c[3])
        : "r"(a0), "r"(a1), "r"(a2), "r"(a3), "r"(b0), "r"(b1));
}

// ------------------------------------------ step-0: h = 0 closed-form prep + zeroing
// A[i][k] = b[i]*W1[k][65];  B[i][k] = b[i]*W1[k][66] + b1[k];  h = 0; msg = 0.
__global__ void __launch_bounds__(256) prep0_kernel(
    const float* __restrict__ b,
    const float* __restrict__ mp_W1, const float* __restrict__ mp_b1)
{
    const int idx = blockIdx.x * 256 + threadIdx.x;   // grid 128 -> 32768 = NND*HM
    const int i = idx >> 6, k = idx & 63;
    const float bi = b[i];
    g_A[idx] = bi * mp_W1[k * 67 + 65];
    g_B[idx] = fmaf(bi, mp_W1[k * 67 + 66], mp_b1[k]);
    if (idx < NND * SD) { g_h0[idx] = 0.f; g_msg[idx] = 0.f; }
}

// ------------------------------------------------- per-step rank-term prep
// A[i][k] = sum_d h[i][d]*W1[k][d]      + b[i]*W1[k][65]
// B[i][k] = sum_d h[i][d]*W1[k][32+d]   + b[i]*W1[k][66] + mp_b1[k]
__global__ void __launch_bounds__(64) prep_kernel(
    const float* __restrict__ hin, const float* __restrict__ b,
    const float* __restrict__ mp_W1, const float* __restrict__ mp_b1)
{
    __shared__ float sh[SD];
    const int i = blockIdx.x, t = threadIdx.x;
    if (t < SD) { sh[t] = hin[i * SD + t]; g_msg[i * SD + t] = 0.f; }
    __syncthreads();
    const float* row = mp_W1 + t * 67;
    float a = 0.f, bb = mp_b1[t];
#pragma unroll
    for (int d = 0; d < SD; d++) { a += row[d] * sh[d]; bb += row[32 + d] * sh[d]; }
    const float bi = b[i];
    g_A[i * HM + t] = a + bi * row[65];
    g_B[i * HM + t] = bb + bi * row[66];
}

// ---------------------------------------------------- pairwise message MLP (tensor cores)
// Block: 256 threads, 32 i-rows x 16 j-cols as 4 sequential subtiles of 32x4.
// Per subtile: warp w -> j_local = w>>1, rows (w&1)*16 .. +16 (proven R8 layout).
__global__ void __launch_bounds__(256) pair_mma_kernel(
    const float* __restrict__ J, const float* __restrict__ mp_W1,
    const float* __restrict__ W2, const float* __restrict__ b2,
    const float* __restrict__ W3, const float* __restrict__ b3)
{
    __shared__ __nv_bfloat16 sW2[HM * 72];   // [k2][k1], padded rows
    __shared__ __nv_bfloat16 sW3[SD * 72];   // [c][k2], padded rows
    __shared__ float sA[TI * 72];            // i-local x 64, padded
    __shared__ float sB[TJS * HM];           // j-local x 64 (per subtile)
    __shared__ float swJ[HM], sb2[HM], sb3[SD];

    const int t = threadIdx.x, w = t >> 5, l = t & 31;
    const int jbase = blockIdx.x * (TJS * NSUB), i0 = blockIdx.y * TI;

    for (int idx = t; idx < HM * HM; idx += 256)
        sW2[(idx >> 6) * 72 + (idx & 63)] = __float2bfloat16(W2[idx]);
    for (int idx = t; idx < SD * HM; idx += 256)
        sW3[(idx >> 6) * 72 + (idx & 63)] = __float2bfloat16(W3[idx]);
    for (int idx = t; idx < TI * HM; idx += 256)
        sA[(idx >> 6) * 72 + (idx & 63)] = g_A[(i0 + (idx >> 6)) * HM + (idx & 63)];
    if (t < HM) { swJ[t] = mp_W1[t * 67 + 64]; sb2[t] = b2[t]; }
    if (t < SD) sb3[t] = b3[t];

    const int jl = w >> 1;            // warp's j (local within subtile)
    const int g = l >> 2, q = l & 3;  // groupID, threadID-in-group
    const int ilo = (w & 1) * 16 + g; // i-local of fragment rows r and r+8
    const int ihi = ilo + 8;

    for (int sub = 0; sub < NSUB; sub++) {
        const int j0 = jbase + sub * TJS;
        __syncthreads();   // previous subtile done reading sB
        for (int idx = t; idx < TJS * HM; idx += 256)
            sB[idx] = g_B[(j0 + (idx >> 6)) * HM + (idx & 63)];
        __syncthreads();

        const float Jlo = J[(i0 + ilo) * NND + (j0 + jl)];
        const float Jhi = J[(i0 + ihi) * NND + (j0 + jl)];

        float C1[8][4];
#pragma unroll
        for (int nt = 0; nt < 8; nt++)
#pragma unroll
            for (int r = 0; r < 4; r++) C1[nt][r] = 0.f;

        // ---------------- stage 1: m2 accum = m1 @ W2^T
#pragma unroll
        for (int kt = 0; kt < 4; kt++) {
            const int c0 = kt * 16 + 2 * q;
            const float2 wj0 = *reinterpret_cast<const float2*>(&swJ[c0]);
            const float2 wj1 = *reinterpret_cast<const float2*>(&swJ[c0 + 8]);
            const float2 al0 = *reinterpret_cast<const float2*>(&sA[ilo * 72 + c0]);
            const float2 al1 = *reinterpret_cast<const float2*>(&sA[ilo * 72 + c0 + 8]);
            const float2 ah0 = *reinterpret_cast<const float2*>(&sA[ihi * 72 + c0]);
            const float2 ah1 = *reinterpret_cast<const float2*>(&sA[ihi * 72 + c0 + 8]);
            const float2 bb0 = *reinterpret_cast<const float2*>(&sB[jl * HM + c0]);
            const float2 bb1 = *reinterpret_cast<const float2*>(&sB[jl * HM + c0 + 8]);

            // m1 = relu(A_i + B_j + J*wJ), packed straight into A fragments
            unsigned a0 = packbf(frelu(fmaf(Jlo, wj0.x, al0.x + bb0.x)),
                                 frelu(fmaf(Jlo, wj0.y, al0.y + bb0.y)));
            unsigned a1 = packbf(frelu(fmaf(Jhi, wj0.x, ah0.x + bb0.x)),
                                 frelu(fmaf(Jhi, wj0.y, ah0.y + bb0.y)));
            unsigned a2 = packbf(frelu(fmaf(Jlo, wj1.x, al1.x + bb1.x)),
                                 frelu(fmaf(Jlo, wj1.y, al1.y + bb1.y)));
            unsigned a3 = packbf(frelu(fmaf(Jhi, wj1.x, ah1.x + bb1.x)),
                                 frelu(fmaf(Jhi, wj1.y, ah1.y + bb1.y)));

#pragma unroll
            for (int nt = 0; nt < 8; nt++) {
                const int n = nt * 8 + g;
                const unsigned b0 = *reinterpret_cast<const unsigned*>(&sW2[n * 72 + kt * 16 + 2 * q]);
                const unsigned b1 = *reinterpret_cast<const unsigned*>(&sW2[n * 72 + kt * 16 + 2 * q + 8]);
                mma16816(C1[nt], a0, a1, a2, a3, b0, b1);
            }
        }

        // ---------------- bias + relu + repack C1 -> stage-2 A fragments
        unsigned A2[4][4];
#pragma unroll
        for (int nt = 0; nt < 8; nt++) {
            const float2 bias = *reinterpret_cast<const float2*>(&sb2[nt * 8 + 2 * q]);
            const float e0 = frelu(C1[nt][0] + bias.x);
            const float e1 = frelu(C1[nt][1] + bias.y);
            const float e2 = frelu(C1[nt][2] + bias.x);
            const float e3 = frelu(C1[nt][3] + bias.y);
            const int kt2 = nt >> 1;
            if ((nt & 1) == 0) { A2[kt2][0] = packbf(e0, e1); A2[kt2][1] = packbf(e2, e3); }
            else               { A2[kt2][2] = packbf(e0, e1); A2[kt2][3] = packbf(e2, e3); }
        }

        // ---------------- stage 2: msg = m2 @ W3^T
        float C2[4][4];
#pragma unroll
        for (int nt = 0; nt < 4; nt++)
#pragma unroll
            for (int r = 0; r < 4; r++) C2[nt][r] = 0.f;

#pragma unroll
        for (int kt = 0; kt < 4; kt++) {
#pragma unroll
            for (int nt = 0; nt < 4; nt++) {
                const int n = nt * 8 + g;
                const unsigned b0 = *reinterpret_cast<const unsigned*>(&sW3[n * 72 + kt * 16 + 2 * q]);
                const unsigned b1 = *reinterpret_cast<const unsigned*>(&sW3[n * 72 + kt * 16 + 2 * q + 8]);
                mma16816(C2[nt], A2[kt][0], A2[kt][1], A2[kt][2], A2[kt][3], b0, b1);
            }
        }

        // ---------------- epilogue: relu(+b3), reduce over warp's 16 i-rows
#pragma unroll
        for (int nt = 0; nt < 4; nt++) {
            const float2 bias = *reinterpret_cast<const float2*>(&sb3[nt * 8 + 2 * q]);
            float s0 = frelu(C2[nt][0] + bias.x) + frelu(C2[nt][2] + bias.x);
            float s1 = frelu(C2[nt][1] + bias.y) + frelu(C2[nt][3] + bias.y);
#pragma unroll
            for (int m = 4; m < 32; m <<= 1) {
                s0 += __shfl_xor_sync(0xffffffffu, s0, m);
                s1 += __shfl_xor_sync(0xffffffffu, s1, m);
            }
            if (g == 0) {
                atomicAdd(&g_msg[(j0 + jl) * SD + nt * 8 + 2 * q],     s0);
                atomicAdd(&g_msg[(j0 + jl) * SD + nt * 8 + 2 * q + 1], s1);
            }
        }
    }
}

// ----------------------------------------------------------------- GRU step
// warp = one d (uniform float4 weight loads), lane = node within 32-node tile
__global__ void __launch_bounds__(256) gru_kernel(
    const float* __restrict__ hin, float* __restrict__ hout,
    const float* __restrict__ Wih, const float* __restrict__ Whh,
    const float* __restrict__ bih, const float* __restrict__ bhh)
{
    __shared__ float sh[32 * 33], sm[32 * 33];
    const int t = threadIdx.x, w = t >> 5, lane = t & 31;
    const int n0 = blockIdx.x * 32;
    const int d = blockIdx.y * 8 + w;
    for (int idx = t; idx < 1024; idx += 256) {
        int r = idx >> 5, c = idx & 31;
        sh[r * 33 + c] = hin[(n0 + r) * SD + c];
        sm[r * 33 + c] = g_msg[(n0 + r) * SD + c];
    }
    __syncthreads();
    const float4* Wr4 = reinterpret_cast<const float4*>(Wih + d * 64);
    const float4* Wz4 = reinterpret_cast<const float4*>(Wih + (32 + d) * 64);
    const float4* Wn4 = reinterpret_cast<const float4*>(Wih + (64 + d) * 64);
    const float4* Vr4 = reinterpret_cast<const float4*>(Whh + d * 32);
    const float4* Vz4 = reinterpret_cast<const float4*>(Whh + (32 + d) * 32);
    const float4* Vn4 = reinterpret_cast<const float4*>(Whh + (64 + d) * 32);
    float ir = bih[d], iz = bih[32 + d], inn = bih[64 + d];
    float hr = bhh[d], hz = bhh[32 + d], hn = bhh[64 + d];
#pragma unroll
    for (int c4 = 0; c4 < 8; c4++) {
        const float4 wrh = Wr4[c4], wrm = Wr4[c4 + 8];
        const float4 wzh = Wz4[c4], wzm = Wz4[c4 + 8];
        const float4 wnh = Wn4[c4], wnm = Wn4[c4 + 8];
        const float4 vr = Vr4[c4], vz = Vz4[c4], vn = Vn4[c4];
        const int c = c4 * 4;
        const float hv0 = sh[lane * 33 + c],     mv0 = sm[lane * 33 + c];
        const float hv1 = sh[lane * 33 + c + 1], mv1 = sm[lane * 33 + c + 1];
        const float hv2 = sh[lane * 33 + c + 2], mv2 = sm[lane * 33 + c + 2];
        const float hv3 = sh[lane * 33 + c + 3], mv3 = sm[lane * 33 + c + 3];
        ir  += wrh.x * hv0 + wrh.y * hv1 + wrh.z * hv2 + wrh.w * hv3
             + wrm.x * mv0 + wrm.y * mv1 + wrm.z * mv2 + wrm.w * mv3;
        iz  += wzh.x * hv0 + wzh.y * hv1 + wzh.z * hv2 + wzh.w * hv3
             + wzm.x * mv0 + wzm.y * mv1 + wzm.z * mv2 + wzm.w * mv3;
        inn += wnh.x * hv0 + wnh.y * hv1 + wnh.z * hv2 + wnh.w * hv3
             + wnm.x * mv0 + wnm.y * mv1 + wnm.z * mv2 + wnm.w * mv3;
        hr  += vr.x * hv0 + vr.y * hv1 + vr.z * hv2 + vr.w * hv3;
        hz  += vz.x * hv0 + vz.y * hv1 + vz.z * hv2 + vz.w * hv3;
        hn  += vn.x * hv0 + vn.y * hv1 + vn.z * hv2 + vn.w * hv3;
    }
    float r = 1.f / (1.f + expf(-(ir + hr)));
    float z = 1.f / (1.f + expf(-(iz + hz)));
    float n = tanhf(inn + r * hn);
    hout[(n0 + lane) * SD + d] = (1.f - z) * n + z * sh[lane * 33 + d];
}

// ----------------------------------------------------------------- readout
__global__ void __launch_bounds__(256) readout_kernel(
    const float* __restrict__ h,
    const float* __restrict__ W1, const float* __restrict__ b1,
    const float* __restrict__ W2, const float* __restrict__ b2,
    const float* __restrict__ W3, const float* __restrict__ b3,
    float* __restrict__ out)
{
    __shared__ float sh[32 * 33];
    __shared__ float sy1[64 * 33];
    __shared__ float sy2[64 * 33];
    const int t = threadIdx.x, w = t >> 5, lane = t & 31;
    const int n0 = blockIdx.x * 32;
    for (int idx = t; idx < 1024; idx += 256) {
        int r = idx >> 5, c = idx & 31;
        sh[r * 33 + c] = h[(n0 + r) * SD + c];
    }
    __syncthreads();
    for (int k = w; k < 64; k += 8) {
        float acc = b1[k];
        const float* Wrow = W1 + k * 32;
#pragma unroll
        for (int c = 0; c < 32; c++) acc += Wrow[c] * sh[lane * 33 + c];
        sy1[k * 33 + lane] = fmaxf(acc, 0.f);
    }
    __syncthreads();
    for (int k = w; k < 64; k += 8) {
        float acc = b2[k];
        const float* Wrow = W2 + k * 64;
#pragma unroll
        for (int c = 0; c < 64; c++) acc += Wrow[c] * sy1[c * 33 + lane];
        sy2[k * 33 + lane] = fmaxf(acc, 0.f);
    }
    __syncthreads();
    if (w < 2) {
        float acc = b3[w];
        const float* Wrow = W3 + w * 64;
#pragma unroll
        for (int c = 0; c < 64; c++) acc += Wrow[c] * sy2[c * 33 + lane];
        float y = fmaxf(acc, 0.f);
        out[(n0 + lane) * 2 + w] = 1.f / (1.f + expf(-y));
    }
}

extern "C" void kernel_launch(void* const* d_in, const int* in_sizes, int n_in,
                              void* d_out, int out_size)
{
    const float* J      = (const float*)d_in[0];
    const float* b      = (const float*)d_in[1];
    const float* mp_W1  = (const float*)d_in[2];
    const float* mp_b1  = (const float*)d_in[3];
    const float* mp_W2  = (const float*)d_in[4];
    const float* mp_b2  = (const float*)d_in[5];
    const float* mp_W3  = (const float*)d_in[6];
    const float* mp_b3  = (const float*)d_in[7];
    const float* Wih    = (const float*)d_in[8];
    const float* Whh    = (const float*)d_in[9];
    const float* bih    = (const float*)d_in[10];
    const float* bhh    = (const float*)d_in[11];
    const float* rW1    = (const float*)d_in[12];
    const float* rb1    = (const float*)d_in[13];
    const float* rW2    = (const float*)d_in[14];
    const float* rb2    = (const float*)d_in[15];
    const float* rW3    = (const float*)d_in[16];
    const float* rb3    = (const float*)d_in[17];
    float* out = (float*)d_out;

    float *p_h0 = nullptr, *p_h1 = nullptr;
    cudaGetSymbolAddress((void**)&p_h0, g_h0);
    cudaGetSymbolAddress((void**)&p_h1, g_h1);

    // step-0 closed-form prep (h = 0): A/B + h/msg zero, replaces init+prep
    prep0_kernel<<<128, 256>>>(b, mp_W1, mp_b1);

    float* hcur = p_h0;
    float* hnext = p_h1;
    dim3 g2(NND / (TJS * NSUB), NND / TI);   // (32, 16) blocks, 4 subtiles each
    for (int s = 0; s < 5; s++) {
        pair_mma_kernel<<<g2, 256>>>(J, mp_W1, mp_W2, mp_b2, mp_W3, mp_b3);
        gru_kernel<<<dim3(16, 4), 256>>>(hcur, hnext, Wih, Whh, bih, bhh);
        if (s < 4)
            prep_kernel<<<NND, 64>>>(hnext, b, mp_W1, mp_b1);
        float* tmp = hcur; hcur = hnext; hnext = tmp;
    }
    readout_kernel<<<16, 256>>>(hcur, rW1, rb1, rW2, rb2, rW3, rb3, out);
}